// round 3
// baseline (speedup 1.0000x reference)
#include <cuda_runtime.h>
#include <cuda_bf16.h>

#ifndef HELM_PI
#define HELM_PI 3.14159265358979323846f
#endif

// out[i] = (a^2 - 2*pi^2) * sin(pi*x0) * sin(pi*x1)
// Each thread processes 8 rows: four independent float4 loads front-batched
// (MLP_p1 = 4), then two float4 streaming stores.
__global__ void __launch_bounds__(256) helm_kernel(
    const float4* __restrict__ in4,   // interleaved [x0,x1] pairs, 2 rows per float4
    const float*  __restrict__ a,
    float4*       __restrict__ out4,  // 4 outputs per float4
    int n8)                            // number of 8-row work items = N/8
{
    int i = blockIdx.x * blockDim.x + threadIdx.x;
    if (i >= n8) return;

    const float pi = HELM_PI;
    float av = __ldg(a);
    float coef = fmaf(av, av, -2.0f * pi * pi);

    // Front-batch 4 independent 128-bit streaming loads (rows 8i .. 8i+7)
    const float4* p = in4 + 4 * (size_t)i;
    float4 v0 = __ldcs(p + 0);
    float4 v1 = __ldcs(p + 1);
    float4 v2 = __ldcs(p + 2);
    float4 v3 = __ldcs(p + 3);

    float4 o0, o1;
    o0.x = coef * __sinf(pi * v0.x) * __sinf(pi * v0.y);
    o0.y = coef * __sinf(pi * v0.z) * __sinf(pi * v0.w);
    o0.z = coef * __sinf(pi * v1.x) * __sinf(pi * v1.y);
    o0.w = coef * __sinf(pi * v1.z) * __sinf(pi * v1.w);
    o1.x = coef * __sinf(pi * v2.x) * __sinf(pi * v2.y);
    o1.y = coef * __sinf(pi * v2.z) * __sinf(pi * v2.w);
    o1.z = coef * __sinf(pi * v3.x) * __sinf(pi * v3.y);
    o1.w = coef * __sinf(pi * v3.z) * __sinf(pi * v3.w);

    float4* q = out4 + 2 * (size_t)i;
    __stcs(q + 0, o0);
    __stcs(q + 1, o1);
}

extern "C" void kernel_launch(void* const* d_in, const int* in_sizes, int n_in,
                              void* d_out, int out_size)
{
    const float* in = (const float*)d_in[0];   // [N,2] float32
    const float* a  = (const float*)d_in[1];   // [1] float32

    int n = in_sizes[0] / 2;   // number of rows (N = 2^24)
    int n8 = n / 8;            // divisible: 2^24 / 8 = 2^21

    const int threads = 256;
    int blocks = (n8 + threads - 1) / threads;

    helm_kernel<<<blocks, threads>>>(
        (const float4*)in, a, (float4*)d_out, n8);
}

// round 4
// speedup vs baseline: 1.0086x; 1.0086x over previous
#include <cuda_runtime.h>
#include <cuda_bf16.h>

#ifndef HELM_PI
#define HELM_PI 3.14159265358979323846f
#endif

// out[i] = (a^2 - 2*pi^2) * sin(pi*x0) * sin(pi*x1)
// R2 geometry (best measured): 4 rows/thread, two independent float4 loads,
// one float4 store. Single change vs R2: streaming (evict-first) store.
__global__ void __launch_bounds__(256) helm_kernel(
    const float4* __restrict__ in4,   // interleaved [x0,x1] pairs, 2 rows per float4
    const float*  __restrict__ a,
    float4*       __restrict__ out4,  // 4 outputs per float4
    int n4)                            // number of output float4s = N/4
{
    int i = blockIdx.x * blockDim.x + threadIdx.x;
    if (i >= n4) return;

    const float pi = HELM_PI;
    float av = __ldg(a);
    float coef = fmaf(av, av, -2.0f * pi * pi);

    float4 v0 = in4[2 * (size_t)i];      // rows 4i, 4i+1
    float4 v1 = in4[2 * (size_t)i + 1];  // rows 4i+2, 4i+3

    float4 o;
    o.x = coef * __sinf(pi * v0.x) * __sinf(pi * v0.y);
    o.y = coef * __sinf(pi * v0.z) * __sinf(pi * v0.w);
    o.z = coef * __sinf(pi * v1.x) * __sinf(pi * v1.y);
    o.w = coef * __sinf(pi * v1.z) * __sinf(pi * v1.w);

    __stcs(out4 + i, o);
}

extern "C" void kernel_launch(void* const* d_in, const int* in_sizes, int n_in,
                              void* d_out, int out_size)
{
    const float* in = (const float*)d_in[0];   // [N,2] float32
    const float* a  = (const float*)d_in[1];   // [1] float32

    int n = in_sizes[0] / 2;   // number of rows (N = 2^24)
    int n4 = n / 4;

    const int threads = 256;
    int blocks = (n4 + threads - 1) / threads;

    helm_kernel<<<blocks, threads>>>(
        (const float4*)in, a, (float4*)d_out, n4);
}

// round 5
// speedup vs baseline: 1.0342x; 1.0254x over previous
#include <cuda_runtime.h>
#include <cuda_bf16.h>

#ifndef HELM_PI
#define HELM_PI 3.14159265358979323846f
#endif

// out[i] = (a^2 - 2*pi^2) * sin(pi*x0) * sin(pi*x1)
// R4 geometry (best measured): 4 rows/thread, two independent float4 loads,
// one float4 store. Change vs R4: streaming (evict-first) LOADS as well —
// input is read exactly once, so L2 retention is pure pollution.
__global__ void __launch_bounds__(256) helm_kernel(
    const float4* __restrict__ in4,   // interleaved [x0,x1] pairs, 2 rows per float4
    const float*  __restrict__ a,
    float4*       __restrict__ out4,  // 4 outputs per float4
    int n4)                            // number of output float4s = N/4
{
    int i = blockIdx.x * blockDim.x + threadIdx.x;
    if (i >= n4) return;

    // Issue the two long-latency streaming data loads FIRST...
    float4 v0 = __ldcs(in4 + 2 * (size_t)i);      // rows 4i, 4i+1
    float4 v1 = __ldcs(in4 + 2 * (size_t)i + 1);  // rows 4i+2, 4i+3

    // ...then the L2-resident scalar load, which overlaps them.
    const float pi = HELM_PI;
    float av = __ldg(a);
    float coef = fmaf(av, av, -2.0f * pi * pi);

    float4 o;
    o.x = coef * __sinf(pi * v0.x) * __sinf(pi * v0.y);
    o.y = coef * __sinf(pi * v0.z) * __sinf(pi * v0.w);
    o.z = coef * __sinf(pi * v1.x) * __sinf(pi * v1.y);
    o.w = coef * __sinf(pi * v1.z) * __sinf(pi * v1.w);

    __stcs(out4 + i, o);
}

extern "C" void kernel_launch(void* const* d_in, const int* in_sizes, int n_in,
                              void* d_out, int out_size)
{
    const float* in = (const float*)d_in[0];   // [N,2] float32
    const float* a  = (const float*)d_in[1];   // [1] float32

    int n = in_sizes[0] / 2;   // number of rows (N = 2^24)
    int n4 = n / 4;

    const int threads = 256;
    int blocks = (n4 + threads - 1) / threads;

    helm_kernel<<<blocks, threads>>>(
        (const float4*)in, a, (float4*)d_out, n4);
}